// round 8
// baseline (speedup 1.0000x reference)
#include <cuda_runtime.h>

// Per-pixel 3x3 conv, kernels shared across channels, edge-replication pad.
// img [1,3,1024,1024] f32, K [9,1024,1024] f32, out [1,3,1024,1024] f32.
//
// R7: RPT=2 row-rolling (72 B/px) with double the CTA count of R6 and reduced
// register pressure (no halo rolling, K taps loaded per window-row) so ~all
// 1024 CTAs are resident in one wave (~40% occ). Balances minimal traffic
// against latency-hiding parallelism.

#define H 1024
#define W 1024
#define HW (H * W)
#define RPT 2              // output rows per thread

__global__ __launch_bounds__(128)
void reblur_kernel(const float* __restrict__ img,
                   const float* __restrict__ ker,
                   float* __restrict__ out)
{
    const int bid  = blockIdx.x;            // 1024 blocks
    const int tid  = threadIdx.x;           // 128 threads -> 512 px of one row
    const int lane = tid & 31;

    const int w0 = (bid & 1) * 512 + tid * 4;   // 4-px column start
    const int h0 = (bid >> 1) * RPT;            // first output row

    const int  wl  = (w0 > 0)     ? w0 - 1 : 0;      // clamped left halo col
    const int  wr  = (w0 + 4 < W) ? w0 + 4 : W - 1;  // clamped right halo col
    const bool isL = (lane == 0);
    const bool isR = (lane == 31);

    // Rolling 3-row image window per channel: rows h-1, h, h+1 (clamped).
    float4 m[3][3];            // [channel][window row]
    int rowi[3];
    #pragma unroll
    for (int j = 0; j < 3; j++) {
        int row = h0 - 1 + j;
        rowi[j] = (row < 0) ? 0 : row;
        #pragma unroll
        for (int c = 0; c < 3; c++)
            m[c][j] = *reinterpret_cast<const float4*>(img + c * HW + rowi[j] * W + w0);
    }

    #pragma unroll
    for (int r = 0; r < RPT; r++) {
        const int h = h0 + r;
        const float* kp = ker + h * W + w0;

        float acc[3][4];
        #pragma unroll
        for (int c = 0; c < 3; c++)
            #pragma unroll
            for (int x = 0; x < 4; x++)
                acc[c][x] = 0.f;

        #pragma unroll
        for (int j = 0; j < 3; j++) {
            // 3 kernel taps for this window row (short live range).
            const float4 k0 = *reinterpret_cast<const float4*>(kp + (j * 3 + 0) * HW);
            const float4 k1 = *reinterpret_cast<const float4*>(kp + (j * 3 + 1) * HW);
            const float4 k2 = *reinterpret_cast<const float4*>(kp + (j * 3 + 2) * HW);

            #pragma unroll
            for (int c = 0; c < 3; c++) {
                const float sl = __shfl_up_sync  (0xffffffffu, m[c][j].w, 1);
                const float sr = __shfl_down_sync(0xffffffffu, m[c][j].x, 1);
                // Boundary lanes: predicated 1-wavefront scalar loads (clamped
                // index also handles the image edge replication for free).
                const float v0 = isL ? img[c * HW + rowi[j] * W + wl] : sl;
                const float v5 = isR ? img[c * HW + rowi[j] * W + wr] : sr;
                const float v1 = m[c][j].x;
                const float v2 = m[c][j].y;
                const float v3 = m[c][j].z;
                const float v4 = m[c][j].w;

                acc[c][0] = fmaf(v0, k0.x, acc[c][0]);
                acc[c][1] = fmaf(v1, k0.y, acc[c][1]);
                acc[c][2] = fmaf(v2, k0.z, acc[c][2]);
                acc[c][3] = fmaf(v3, k0.w, acc[c][3]);

                acc[c][0] = fmaf(v1, k1.x, acc[c][0]);
                acc[c][1] = fmaf(v2, k1.y, acc[c][1]);
                acc[c][2] = fmaf(v3, k1.z, acc[c][2]);
                acc[c][3] = fmaf(v4, k1.w, acc[c][3]);

                acc[c][0] = fmaf(v2, k2.x, acc[c][0]);
                acc[c][1] = fmaf(v3, k2.y, acc[c][1]);
                acc[c][2] = fmaf(v4, k2.z, acc[c][2]);
                acc[c][3] = fmaf(v5, k2.w, acc[c][3]);
            }
        }

        #pragma unroll
        for (int c = 0; c < 3; c++) {
            float4 o;
            o.x = acc[c][0]; o.y = acc[c][1]; o.z = acc[c][2]; o.w = acc[c][3];
            *reinterpret_cast<float4*>(out + c * HW + h * W + w0) = o;
        }

        // Roll window: shift up, fetch row h+2 (clamped).
        if (r < RPT - 1) {
            int nrow = h + 2;
            nrow = (nrow > H - 1) ? H - 1 : nrow;
            rowi[0] = rowi[1]; rowi[1] = rowi[2]; rowi[2] = nrow;
            #pragma unroll
            for (int c = 0; c < 3; c++) {
                m[c][0] = m[c][1];
                m[c][1] = m[c][2];
                m[c][2] = *reinterpret_cast<const float4*>(img + c * HW + nrow * W + w0);
            }
        }
    }
}

extern "C" void kernel_launch(void* const* d_in, const int* in_sizes, int n_in,
                              void* d_out, int out_size)
{
    const float* img = (const float*)d_in[0];   // [1,3,1024,1024]
    const float* ker = (const float*)d_in[1];   // [9,1024,1024]
    float* out = (float*)d_out;                 // [1,3,1024,1024]

    // 2 width-halves x 512 row-groups = 1024 CTAs of 128 threads.
    reblur_kernel<<<1024, 128>>>(img, ker, out);
}

// round 9
// speedup vs baseline: 2.0431x; 2.0431x over previous
#include <cuda_runtime.h>

// Per-pixel 3x3 conv, kernels shared across channels, edge-replication pad.
// img [1,3,1024,1024] f32, K [9,1024,1024] f32, out [1,3,1024,1024] f32.
//
// R9 = R6 (best: register row-rolling, RPT=4, front-batched loads) + software
// pipelining: K taps double-buffered in registers; row h+1's 9 K loads and the
// next window's image/halo loads are issued BEFORE row h's FMAs, so each warp
// keeps ~9-13 LDGs continuously in flight (hides ~600cyc DRAM latency at low occ).

#define H 1024
#define W 1024
#define HW (H * W)
#define RPT 4              // output rows per thread

__global__ __launch_bounds__(128)
void reblur_kernel(const float* __restrict__ img,
                   const float* __restrict__ ker,
                   float* __restrict__ out)
{
    const int bid  = blockIdx.x;           // 512 blocks
    const int tid  = threadIdx.x;          // 128 threads -> 512 px of one row
    const int lane = tid & 31;

    const int w0 = (bid & 1) * 512 + tid * 4;   // 4-px column start
    const int h0 = (bid >> 1) * RPT;            // first output row

    const int  wl  = (w0 > 0)     ? w0 - 1 : 0;      // clamped left halo col
    const int  wr  = (w0 + 4 < W) ? w0 + 4 : W - 1;  // clamped right halo col
    const bool isL = (lane == 0);
    const bool isR = (lane == 31);

    float4 m [3][3];           // image window [channel][row: h-1,h,h+1]
    float  lv[3][3], rv[3][3]; // rolled boundary halos (lanes 0/31)
    float4 kbuf[2][9];         // double-buffered per-pixel K taps

    // ---- init: window rows h0-1,h0,h0+1 and row h0's K taps, all in flight --
    #pragma unroll
    for (int j = 0; j < 3; j++) {
        int row = h0 - 1 + j;
        row = (row < 0) ? 0 : row;
        #pragma unroll
        for (int c = 0; c < 3; c++) {
            const float* p = img + c * HW + row * W;
            m[c][j]  = *reinterpret_cast<const float4*>(p + w0);
            lv[c][j] = isL ? p[wl] : 0.f;
            rv[c][j] = isR ? p[wr] : 0.f;
        }
    }
    {
        const float* kp = ker + h0 * W + w0;
        #pragma unroll
        for (int t = 0; t < 9; t++)
            kbuf[0][t] = *reinterpret_cast<const float4*>(kp + t * HW);
    }

    #pragma unroll
    for (int r = 0; r < RPT; r++) {
        const int h   = h0 + r;
        const int cur = r & 1;

        // ---- prefetch phase: next row's K taps + next window row ----------
        if (r < RPT - 1) {
            const float* kp = ker + (h + 1) * W + w0;
            #pragma unroll
            for (int t = 0; t < 9; t++)
                kbuf[cur ^ 1][t] = *reinterpret_cast<const float4*>(kp + t * HW);
        }
        float4 mn[3]; float lvn[3], rvn[3];
        if (r < RPT - 1) {
            int nrow = h + 2;
            nrow = (nrow > H - 1) ? H - 1 : nrow;
            #pragma unroll
            for (int c = 0; c < 3; c++) {
                const float* p = img + c * HW + nrow * W;
                mn[c]  = *reinterpret_cast<const float4*>(p + w0);
                lvn[c] = isL ? p[wl] : 0.f;
                rvn[c] = isR ? p[wr] : 0.f;
            }
        }

        // ---- compute row h with current K buffer --------------------------
        #pragma unroll
        for (int c = 0; c < 3; c++) {
            float acc0 = 0.f, acc1 = 0.f, acc2 = 0.f, acc3 = 0.f;
            #pragma unroll
            for (int j = 0; j < 3; j++) {
                const float sl = __shfl_up_sync  (0xffffffffu, m[c][j].w, 1);
                const float sr = __shfl_down_sync(0xffffffffu, m[c][j].x, 1);
                const float v0 = isL ? lv[c][j] : sl;
                const float v5 = isR ? rv[c][j] : sr;
                const float v1 = m[c][j].x;
                const float v2 = m[c][j].y;
                const float v3 = m[c][j].z;
                const float v4 = m[c][j].w;

                float4 kv;
                kv = kbuf[cur][j * 3 + 0];
                acc0 = fmaf(v0, kv.x, acc0);
                acc1 = fmaf(v1, kv.y, acc1);
                acc2 = fmaf(v2, kv.z, acc2);
                acc3 = fmaf(v3, kv.w, acc3);
                kv = kbuf[cur][j * 3 + 1];
                acc0 = fmaf(v1, kv.x, acc0);
                acc1 = fmaf(v2, kv.y, acc1);
                acc2 = fmaf(v3, kv.z, acc2);
                acc3 = fmaf(v4, kv.w, acc3);
                kv = kbuf[cur][j * 3 + 2];
                acc0 = fmaf(v2, kv.x, acc0);
                acc1 = fmaf(v3, kv.y, acc1);
                acc2 = fmaf(v4, kv.z, acc2);
                acc3 = fmaf(v5, kv.w, acc3);
            }
            float4 o; o.x = acc0; o.y = acc1; o.z = acc2; o.w = acc3;
            *reinterpret_cast<float4*>(out + c * HW + h * W + w0) = o;
        }

        // ---- roll window with prefetched row ------------------------------
        if (r < RPT - 1) {
            #pragma unroll
            for (int c = 0; c < 3; c++) {
                m[c][0]  = m[c][1];  m[c][1]  = m[c][2];  m[c][2]  = mn[c];
                lv[c][0] = lv[c][1]; lv[c][1] = lv[c][2]; lv[c][2] = lvn[c];
                rv[c][0] = rv[c][1]; rv[c][1] = rv[c][2]; rv[c][2] = rvn[c];
            }
        }
    }
}

extern "C" void kernel_launch(void* const* d_in, const int* in_sizes, int n_in,
                              void* d_out, int out_size)
{
    const float* img = (const float*)d_in[0];   // [1,3,1024,1024]
    const float* ker = (const float*)d_in[1];   // [9,1024,1024]
    float* out = (float*)d_out;                 // [1,3,1024,1024]

    // 2 width-halves x 256 row-groups = 512 CTAs of 128 threads.
    reblur_kernel<<<512, 128>>>(img, ker, out);
}